// round 9
// baseline (speedup 1.0000x reference)
#include <cuda_runtime.h>
#include <math.h>

#define Nn 1024
#define Ff 64
#define ALPHA 0.2f

// ---------------------------------------------------------------------------
// Single fully-fused GAT kernel. grid 256 (4 rows/block), 256 threads.
// Uses the identity P@(hW) = (P@h)@W so every block is self-contained:
//   phase 0: W -> SMEM; Wa1 = W@a1, Wa2 = W@a2
//   phase 1: e2_j = h_j . Wa2 (all 1024 j), e1_i = h_i . Wa1 (4 rows)
//   phase 2: 2 j-halves of 512: p-tile (unnormalized softmax weights,
//            dup-pairs in SMEM) then U += p . h  (fma.f32x2 register tiles)
//   phase 3: 16-split tree reduction -> U (4x64 in SMEM), dsum
//   phase 4: out_i = elu( (U_i @ W) / d_i )   (W still in SMEM)
// No inter-block communication, one launch.
// ---------------------------------------------------------------------------
__global__ __launch_bounds__(256) void gat_one(
        const float* __restrict__ h, const int* __restrict__ adj,
        const float* __restrict__ W, const float* __restrict__ a,
        float* __restrict__ out) {
    __shared__ __align__(16) float Ws[64 * 64];          // 16KB
    __shared__ __align__(16) float psbuf[512 * 8 + 1024]; // ps(16KB) + e2s(4KB); red overlays
    __shared__ float as_[128];
    __shared__ float wa1s[64], wa2s[64];
    __shared__ float e1s[4];
    __shared__ float wpart[8][4];
    __shared__ __align__(16) float Us[4][64];

    float* ps  = psbuf;            // [0, 4096): p dup-pairs for current half
    float* e2s = psbuf + 4096;     // [4096, 5120): e2 for all 1024 j
    float* red = psbuf;            // overlays ps+e2s after GEMM (4224 <= 5120)

    int t = threadIdx.x;
    int rg = blockIdx.x;
    int r0 = rg * 4;
    int fi = t & 15;
    int jg = t >> 4;

    // ---- hoisted adj loads: 4 rows x 4 j-columns (t + 256c) ----
    int av[4][4];
#pragma unroll
    for (int c = 0; c < 4; c++)
#pragma unroll
        for (int ii = 0; ii < 4; ii++)
            av[c][ii] = __ldg(&adj[(size_t)(r0 + ii) * Nn + c * 256 + t]);

    // ---- phase 0a: W -> SMEM, a -> SMEM ----
#pragma unroll
    for (int k = 0; k < 4; k++)
        ((float4*)Ws)[t + k * 256] = ((const float4*)W)[t + k * 256];
    if (t < 128) as_[t] = a[t];
    __syncthreads();

    // ---- phase 0b: Wa1[k] = W[k,:].a1 ; Wa2[k] = W[k,:].a2 ----
    if (t < 128) {
        int k = t & 63;
        const float* av_ = (t < 64) ? as_ : (as_ + 64);
        float acc0 = 0.f, acc1 = 0.f;
#pragma unroll
        for (int f = 0; f < 64; f += 2) {
            acc0 += Ws[k * 64 + f]     * av_[f];
            acc1 += Ws[k * 64 + f + 1] * av_[f + 1];
        }
        if (t < 64) wa1s[k] = acc0 + acc1; else wa2s[k] = acc0 + acc1;
    }
    __syncthreads();

    // ---- phase 1a: e2_j = h_j . Wa2 for j = t + 256c ----
    const float4* wa2s4 = (const float4*)wa2s;
#pragma unroll
    for (int c = 0; c < 4; c++) {
        int j = c * 256 + t;
        const float4* hj = (const float4*)(h + (size_t)j * Ff);
        float a0 = 0.f, a1v = 0.f, a2v = 0.f, a3v = 0.f;
#pragma unroll
        for (int q = 0; q < 16; q += 4) {
            float4 h0 = __ldg(&hj[q]),     h1 = __ldg(&hj[q + 1]);
            float4 h2 = __ldg(&hj[q + 2]), h3 = __ldg(&hj[q + 3]);
            float4 w0 = wa2s4[q],     w1 = wa2s4[q + 1];
            float4 w2 = wa2s4[q + 2], w3 = wa2s4[q + 3];
            a0 += h0.x * w0.x + h0.y * w0.y + h0.z * w0.z + h0.w * w0.w;
            a1v += h1.x * w1.x + h1.y * w1.y + h1.z * w1.z + h1.w * w1.w;
            a2v += h2.x * w2.x + h2.y * w2.y + h2.z * w2.z + h2.w * w2.w;
            a3v += h3.x * w3.x + h3.y * w3.y + h3.z * w3.z + h3.w * w3.w;
        }
        e2s[j] = (a0 + a1v) + (a2v + a3v);
    }
    // ---- phase 1b: e1_i = h_i . Wa1 for the 4 block rows (warps 0-3) ----
    if (t < 128) {
        int i = t >> 5, ln = t & 31;
        const float* hr = h + (size_t)(r0 + i) * Ff;
        float p = __ldg(&hr[ln]) * wa1s[ln] + __ldg(&hr[ln + 32]) * wa1s[ln + 32];
#pragma unroll
        for (int o = 16; o; o >>= 1) p += __shfl_xor_sync(0xffffffffu, p, o);
        if (ln == 0) e1s[i] = p;
    }
    __syncthreads();

    float e1r0 = e1s[0], e1r1 = e1s[1], e1r2 = e1s[2], e1r3 = e1s[3];
    float d0 = 0.f, d1 = 0.f, d2 = 0.f, d3 = 0.f;
    unsigned long long acc_lo[4] = {0ull, 0ull, 0ull, 0ull};
    unsigned long long acc_hi[4] = {0ull, 0ull, 0ull, 0ull};
    const ulonglong2* hL = (const ulonglong2*)h;

    // ---- phase 2: two j-halves of 512 ----
#pragma unroll
    for (int jh = 0; jh < 2; jh++) {
        int jb = jh * 512;
        // p tile for this half
#pragma unroll
        for (int q = 0; q < 2; q++) {
            int c = jh * 2 + q;
            int j = q * 256 + t;                 // local j within half
            float e2 = e2s[jb + j];
            float s0 = e1r0 + e2; s0 = (s0 > 0.f) ? s0 : ALPHA * s0;
            float s1 = e1r1 + e2; s1 = (s1 > 0.f) ? s1 : ALPHA * s1;
            float s2 = e1r2 + e2; s2 = (s2 > 0.f) ? s2 : ALPHA * s2;
            float s3 = e1r3 + e2; s3 = (s3 > 0.f) ? s3 : ALPHA * s3;
            float p0 = (av[c][0] > 0) ? __expf(s0) : 0.f;
            float p1 = (av[c][1] > 0) ? __expf(s1) : 0.f;
            float p2 = (av[c][2] > 0) ? __expf(s2) : 0.f;
            float p3 = (av[c][3] > 0) ? __expf(s3) : 0.f;
            d0 += p0; d1 += p1; d2 += p2; d3 += p3;
            float* bp = &ps[j * 8];
            *(float4*)(bp)     = make_float4(p0, p0, p1, p1);
            *(float4*)(bp + 4) = make_float4(p2, p2, p3, p3);
        }
        __syncthreads();

        // GEMM over this half: 32 j-steps
#pragma unroll 8
        for (int k = 0; k < 32; k++) {
            int j = k * 16 + jg;
            ulonglong2 hv = hL[(size_t)(jb + j) * 16 + fi];
            ulonglong2 pA = *(const ulonglong2*)&ps[j * 8];
            ulonglong2 pB = *(const ulonglong2*)&ps[j * 8 + 4];
            asm("fma.rn.f32x2 %0,%1,%2,%0;" : "+l"(acc_lo[0]) : "l"(pA.x), "l"(hv.x));
            asm("fma.rn.f32x2 %0,%1,%2,%0;" : "+l"(acc_hi[0]) : "l"(pA.x), "l"(hv.y));
            asm("fma.rn.f32x2 %0,%1,%2,%0;" : "+l"(acc_lo[1]) : "l"(pA.y), "l"(hv.x));
            asm("fma.rn.f32x2 %0,%1,%2,%0;" : "+l"(acc_hi[1]) : "l"(pA.y), "l"(hv.y));
            asm("fma.rn.f32x2 %0,%1,%2,%0;" : "+l"(acc_lo[2]) : "l"(pB.x), "l"(hv.x));
            asm("fma.rn.f32x2 %0,%1,%2,%0;" : "+l"(acc_hi[2]) : "l"(pB.x), "l"(hv.y));
            asm("fma.rn.f32x2 %0,%1,%2,%0;" : "+l"(acc_lo[3]) : "l"(pB.y), "l"(hv.x));
            asm("fma.rn.f32x2 %0,%1,%2,%0;" : "+l"(acc_hi[3]) : "l"(pB.y), "l"(hv.y));
        }
        __syncthreads();   // ps reuse / red overlay safety
    }

    // ---- dsum reduction ----
#pragma unroll
    for (int o = 16; o; o >>= 1) {
        d0 += __shfl_xor_sync(0xffffffffu, d0, o);
        d1 += __shfl_xor_sync(0xffffffffu, d1, o);
        d2 += __shfl_xor_sync(0xffffffffu, d2, o);
        d3 += __shfl_xor_sync(0xffffffffu, d3, o);
    }
    if ((t & 31) == 0) {
        int w = t >> 5;
        wpart[w][0] = d0; wpart[w][1] = d1; wpart[w][2] = d2; wpart[w][3] = d3;
    }

    // ---- phase 3: 16-split tree reduction (red overlays psbuf) ----
    float af[4][4];
#pragma unroll
    for (int ii = 0; ii < 4; ii++) {
        float2 lo = *(float2*)&acc_lo[ii];
        float2 hi = *(float2*)&acc_hi[ii];
        af[ii][0] = lo.x; af[ii][1] = lo.y; af[ii][2] = hi.x; af[ii][3] = hi.y;
        *(float4*)&red[jg * 264 + ii * 64 + fi * 4] = make_float4(lo.x, lo.y, hi.x, hi.y);
    }
    __syncthreads();
#pragma unroll
    for (int sh = 8; sh >= 1; sh >>= 1) {
        if (jg >= sh && jg < 2 * sh) {
#pragma unroll
            for (int ii = 0; ii < 4; ii++)
                *(float4*)&red[((jg - sh) * 264) + ii * 64 + fi * 4] =
                    make_float4(af[ii][0], af[ii][1], af[ii][2], af[ii][3]);
        }
        __syncthreads();
        if (jg < sh) {
#pragma unroll
            for (int ii = 0; ii < 4; ii++) {
                float4 v = *(const float4*)&red[(jg * 264) + ii * 64 + fi * 4];
                af[ii][0] += v.x; af[ii][1] += v.y; af[ii][2] += v.z; af[ii][3] += v.w;
            }
        }
        __syncthreads();
    }
    if (jg == 0) {
#pragma unroll
        for (int ii = 0; ii < 4; ii++)
            *(float4*)&Us[ii][fi * 4] = make_float4(af[ii][0], af[ii][1], af[ii][2], af[ii][3]);
    }
    __syncthreads();

    // ---- phase 4: out_i = elu( (U_i @ W) / d_i ) ----
    {
        int oii = t >> 6;
        int of  = t & 63;
        float dd = 0.f;
#pragma unroll
        for (int w2 = 0; w2 < 8; w2++) dd += wpart[w2][oii];
        float inv = 1.0f / dd;

        float v0 = 0.f, v1 = 0.f, v2 = 0.f, v3 = 0.f;
#pragma unroll
        for (int k = 0; k < 64; k += 4) {
            v0 += Us[oii][k]     * Ws[k * 64 + of];
            v1 += Us[oii][k + 1] * Ws[(k + 1) * 64 + of];
            v2 += Us[oii][k + 2] * Ws[(k + 2) * 64 + of];
            v3 += Us[oii][k + 3] * Ws[(k + 3) * 64 + of];
        }
        float val = ((v0 + v1) + (v2 + v3)) * inv;
        val = (val > 0.f) ? val : expm1f(val);
        out[(size_t)(r0 + oii) * Ff + of] = val;
    }
}

// ---------------------------------------------------------------------------
extern "C" void kernel_launch(void* const* d_in, const int* in_sizes, int n_in,
                              void* d_out, int out_size) {
    const float* h   = (const float*)d_in[0];
    const int*   adj = (const int*)d_in[1];
    const float* W   = (const float*)d_in[2];
    const float* a   = (const float*)d_in[3];
    float* out = (float*)d_out;

    gat_one<<<256, 256>>>(h, adj, W, a, out);
}

// round 10
// speedup vs baseline: 2.2441x; 2.2441x over previous
#include <cuda_runtime.h>
#include <math.h>

#define Nn 1024
#define Ff 64
#define ALPHA 0.2f

// scratch
__device__ __align__(16) float g_Wh[Nn * Ff];
__device__ float g_e1[Nn];
__device__ float g_e2[Nn];

// ---------------------------------------------------------------------------
// k1: Wh = h @ W ; e1 = Wh@a1 ; e2 = Wh@a2. grid 256 (4 rows/block),
// SMEM-staged W, 1 output/thread.
// ---------------------------------------------------------------------------
__global__ __launch_bounds__(256) void gat_k1(const float* __restrict__ h,
                                              const float* __restrict__ W,
                                              const float* __restrict__ a) {
    __shared__ float Ws[Ff * Ff];
    __shared__ float hs[4 * Ff];
    __shared__ float a1s[Ff], a2s[Ff];
    __shared__ float es1[8], es2[8];
    int t = threadIdx.x;
    int row0 = blockIdx.x * 4;

#pragma unroll
    for (int k = 0; k < 4; k++)
        ((float4*)Ws)[t + k * 256] = ((const float4*)W)[t + k * 256];
    hs[t] = h[row0 * Ff + t];
    if (t < Ff) { a1s[t] = a[t]; a2s[t] = a[Ff + t]; }
    __syncthreads();

    int ii = t >> 6;
    int f  = t & 63;
    float acc = 0.f;
#pragma unroll
    for (int k = 0; k < Ff; k++)
        acc += hs[ii * Ff + k] * Ws[k * Ff + f];
    int row = row0 + ii;
    g_Wh[row * Ff + f] = acc;

    float p1 = acc * a1s[f];
    float p2 = acc * a2s[f];
#pragma unroll
    for (int o = 16; o; o >>= 1) {
        p1 += __shfl_xor_sync(0xffffffffu, p1, o);
        p2 += __shfl_xor_sync(0xffffffffu, p2, o);
    }
    int w = t >> 5;
    if ((t & 31) == 0) { es1[w] = p1; es2[w] = p2; }
    __syncthreads();
    if (t < 4) {
        g_e1[row0 + t] = es1[2 * t] + es1[2 * t + 1];
        g_e2[row0 + t] = es2[2 * t] + es2[2 * t + 1];
    }
}

// ---------------------------------------------------------------------------
// k2: fused attention: out = elu( (P@Wh) / rowsum ), unnormalized softmax.
// grid 256 (4 rows/block, full j range), 512 threads (16 warps -> 2 CTA/SM).
// p-tile: thread t -> j = t&255; half = t>>8 computes rows {2h, 2h+1}.
// GEMM: thread (fi = t&15, jg = (t>>4)&31), 8 j-steps per 256-j tile,
// Wh double-buffered LDG.128 (ulonglong2), p dup-pairs broadcast LDS.128.
// Reduction: 32 splits -> two half-sums of 16 -> SMEM combine -> elu.
// ---------------------------------------------------------------------------
__global__ __launch_bounds__(512, 2) void gat_k2(const int* __restrict__ adj,
                                                 float* __restrict__ out) {
    __shared__ __align__(16) float ps[256 * 8];    // 8KB p dup-pairs
    __shared__ __align__(16) float red[32 * 264];  // 33.8KB split buffer
    __shared__ float red2[256];
    __shared__ float wpart[16][2];
    __shared__ float dfin[4];

    int t = threadIdx.x;
    int r0 = blockIdx.x * 4;
    int half = t >> 8;               // 0: rows 0,1 ; 1: rows 2,3
    int jc = t & 255;                // j within tile
    int fi = t & 15;
    int jg = (t >> 4) & 31;

    // ---- hoisted loads: adj[4 tiles][2 rows], e2[4 tiles], e1[2] ----
    int av[4][2];
    float e2v[4];
#pragma unroll
    for (int jt = 0; jt < 4; jt++) {
        const int* ac = adj + jt * 256 + jc;
        av[jt][0] = __ldg(ac + (size_t)(r0 + half * 2 + 0) * Nn);
        av[jt][1] = __ldg(ac + (size_t)(r0 + half * 2 + 1) * Nn);
        e2v[jt] = __ldg(&g_e2[jt * 256 + jc]);
    }
    float e1a = __ldg(&g_e1[r0 + half * 2 + 0]);
    float e1b = __ldg(&g_e1[r0 + half * 2 + 1]);

    float da = 0.f, db = 0.f;
    unsigned long long acc_lo[4] = {0ull, 0ull, 0ull, 0ull};
    unsigned long long acc_hi[4] = {0ull, 0ull, 0ull, 0ull};
    const ulonglong2* WhL = (const ulonglong2*)g_Wh;

    // prefetch first Wh batch (tile 0, steps 0..3)
    ulonglong2 whbuf[4];
#pragma unroll
    for (int kk = 0; kk < 4; kk++)
        whbuf[kk] = WhL[(size_t)(kk * 32 + jg) * 16 + fi];

#pragma unroll
    for (int jt = 0; jt < 4; jt++) {
        if (jt) __syncthreads();          // ps reuse guard

        // ---- p half-tile from preloaded regs ----
        {
            float e2 = e2v[jt];
            float s0 = e1a + e2; s0 = (s0 > 0.f) ? s0 : ALPHA * s0;
            float s1 = e1b + e2; s1 = (s1 > 0.f) ? s1 : ALPHA * s1;
            float p0 = (av[jt][0] > 0) ? __expf(s0) : 0.f;
            float p1 = (av[jt][1] > 0) ? __expf(s1) : 0.f;
            da += p0; db += p1;
            *(float4*)&ps[jc * 8 + half * 4] = make_float4(p0, p0, p1, p1);
        }
        __syncthreads();

        // ---- GEMM: 8 j-steps in 2 double-buffered batches ----
#pragma unroll
        for (int kb = 0; kb < 2; kb++) {
            ulonglong2 c[4];
#pragma unroll
            for (int kk = 0; kk < 4; kk++) c[kk] = whbuf[kk];

            if (kb == 0) {
#pragma unroll
                for (int kk = 0; kk < 4; kk++)
                    whbuf[kk] = WhL[(size_t)(jt * 256 + (4 + kk) * 32 + jg) * 16 + fi];
            } else if (jt < 3) {
#pragma unroll
                for (int kk = 0; kk < 4; kk++)
                    whbuf[kk] = WhL[(size_t)((jt + 1) * 256 + kk * 32 + jg) * 16 + fi];
            }

#pragma unroll
            for (int kk = 0; kk < 4; kk++) {
                int j = (kb * 4 + kk) * 32 + jg;
                ulonglong2 wh = c[kk];
                ulonglong2 pA = *(const ulonglong2*)&ps[j * 8];
                ulonglong2 pB = *(const ulonglong2*)&ps[j * 8 + 4];
                asm("fma.rn.f32x2 %0,%1,%2,%0;" : "+l"(acc_lo[0]) : "l"(pA.x), "l"(wh.x));
                asm("fma.rn.f32x2 %0,%1,%2,%0;" : "+l"(acc_hi[0]) : "l"(pA.x), "l"(wh.y));
                asm("fma.rn.f32x2 %0,%1,%2,%0;" : "+l"(acc_lo[1]) : "l"(pA.y), "l"(wh.x));
                asm("fma.rn.f32x2 %0,%1,%2,%0;" : "+l"(acc_hi[1]) : "l"(pA.y), "l"(wh.y));
                asm("fma.rn.f32x2 %0,%1,%2,%0;" : "+l"(acc_lo[2]) : "l"(pB.x), "l"(wh.x));
                asm("fma.rn.f32x2 %0,%1,%2,%0;" : "+l"(acc_hi[2]) : "l"(pB.x), "l"(wh.y));
                asm("fma.rn.f32x2 %0,%1,%2,%0;" : "+l"(acc_lo[3]) : "l"(pB.y), "l"(wh.x));
                asm("fma.rn.f32x2 %0,%1,%2,%0;" : "+l"(acc_hi[3]) : "l"(pB.y), "l"(wh.y));
            }
        }
    }

    // ---- dsum: warp-reduce (each warp covers 32 jc's for its 2 rows) ----
#pragma unroll
    for (int o = 16; o; o >>= 1) {
        da += __shfl_xor_sync(0xffffffffu, da, o);
        db += __shfl_xor_sync(0xffffffffu, db, o);
    }
    if ((t & 31) == 0) {
        int w = t >> 5;                  // 0..15
        wpart[w][0] = da;
        wpart[w][1] = db;
    }

    // ---- write register tiles to red[jg] ----
#pragma unroll
    for (int ii = 0; ii < 4; ii++) {
        float2 lo = *(float2*)&acc_lo[ii];
        float2 hi = *(float2*)&acc_hi[ii];
        *(float4*)&red[jg * 264 + ii * 64 + fi * 4] = make_float4(lo.x, lo.y, hi.x, hi.y);
    }
    __syncthreads();

    // ---- combine dsums: dfin[r] ----
    if (t < 4) {
        int hh = t >> 1, rr = t & 1;
        float dd = 0.f;
#pragma unroll
        for (int w2 = 0; w2 < 8; w2++) dd += wpart[hh * 8 + w2][rr];
        dfin[t] = dd;
    }

    // ---- reduce 32 splits: each half sums 16, then combine ----
    {
        int e = t & 255;                 // output element of the 4x64 tile
        float val = 0.f;
#pragma unroll
        for (int g = 0; g < 16; g++)
            val += red[(half * 16 + g) * 264 + e];
        if (half == 1) red2[e] = val;
        __syncthreads();
        if (half == 0) {
            val += red2[e];
            int oii = e >> 6;
            int of  = e & 63;
            float r = val / dfin[oii];
            r = (r > 0.f) ? r : expm1f(r);
            out[(size_t)(r0 + oii) * Ff + of] = r;
        }
    }
}

// ---------------------------------------------------------------------------
extern "C" void kernel_launch(void* const* d_in, const int* in_sizes, int n_in,
                              void* d_out, int out_size) {
    const float* h   = (const float*)d_in[0];
    const int*   adj = (const int*)d_in[1];
    const float* W   = (const float*)d_in[2];
    const float* a   = (const float*)d_in[3];
    float* out = (float*)d_out;

    gat_k1<<<256, 256>>>(h, W, a);
    gat_k2<<<256, 512>>>(adj, out);
}